// round 14
// baseline (speedup 1.0000x reference)
#include <cuda_runtime.h>
#include <cuda_bf16.h>
#include <math.h>
#include <stdint.h>

#define Bdim 64
#define Tdim 512
#define Idim 1024
#define Hdim 1024
#define M_TOT (Bdim*Tdim)   /* 32768 */

typedef unsigned long long u64;

/* ================= PTX helpers (all base-sm_103-safe: sm_80 era) ================= */
__device__ __forceinline__ uint32_t smem_u32(const void* p) {
    uint32_t a;
    asm("{ .reg .u64 t; cvta.to.shared.u64 t, %1; cvt.u32.u64 %0, t; }" : "=r"(a) : "l"(p));
    return a;
}
#define LDSM_X4(r, addr) \
    asm volatile("ldmatrix.sync.aligned.m8n8.x4.shared.b16 {%0,%1,%2,%3}, [%4];" \
        : "=r"((r)[0]), "=r"((r)[1]), "=r"((r)[2]), "=r"((r)[3]) : "r"(addr))
#define LDSM_X2(r, addr) \
    asm volatile("ldmatrix.sync.aligned.m8n8.x2.shared.b16 {%0,%1}, [%2];" \
        : "=r"((r)[0]), "=r"((r)[1]) : "r"(addr))
__device__ __forceinline__ void mma16816(float* c, const uint32_t* a, const uint32_t* b) {
    asm volatile(
        "mma.sync.aligned.m16n8k16.row.col.f32.bf16.bf16.f32 "
        "{%0,%1,%2,%3}, {%4,%5,%6,%7}, {%8,%9}, {%0,%1,%2,%3};"
        : "+f"(c[0]), "+f"(c[1]), "+f"(c[2]), "+f"(c[3])
        : "r"(a[0]), "r"(a[1]), "r"(a[2]), "r"(a[3]), "r"(b[0]), "r"(b[1]));
}
#define CP_ASYNC16(dst, src) \
    asm volatile("cp.async.cg.shared.global [%0], [%1], 16;" :: "r"(dst), "l"(src))
#define CP_COMMIT() asm volatile("cp.async.commit_group;" ::: "memory")
#define CP_WAIT(N)  asm volatile("cp.async.wait_group %0;" :: "n"(N) : "memory")

/* ---- scratch (device globals: no allocation allowed) ---- */
__device__ float g_xw[(size_t)M_TOT * Hdim];              /* 128 MB */
__device__ __nv_bfloat16 g_xhi[(size_t)M_TOT * Idim];     /* 64 MB */
__device__ __nv_bfloat16 g_xlo[(size_t)M_TOT * Idim];     /* 64 MB */
__device__ __nv_bfloat16 g_whi[(size_t)Hdim * Idim];
__device__ __nv_bfloat16 g_wlo[(size_t)Hdim * Idim];
__device__ __nv_bfloat16 g_uhi[(size_t)Hdim * Hdim];
__device__ __nv_bfloat16 g_ulo[(size_t)Hdim * Hdim];
__device__ __nv_bfloat16 g_hhi[2][Bdim * Hdim];           /* h3 state hi, ping-pong */
__device__ __nv_bfloat16 g_hlo[2][Bdim * Hdim];           /* h3 state lo */
__device__ volatile unsigned g_flag[4][32];               /* per-(group,CTA) monotonic flags */

/* ================= fp32 -> bf16 hi/lo split ================= */
__global__ __launch_bounds__(256) void cvt_split_kernel(
    const float* __restrict__ src, int which, int n4)
{
    __nv_bfloat16 *hi, *lo;
    if (which == 0)      { hi = g_xhi; lo = g_xlo; }
    else if (which == 1) { hi = g_whi; lo = g_wlo; }
    else                 { hi = g_uhi; lo = g_ulo; }
    for (int i = blockIdx.x * 256 + threadIdx.x; i < n4; i += gridDim.x * 256) {
        float4 v = ((const float4*)src)[i];
        __nv_bfloat16 h0 = __float2bfloat16_rn(v.x);
        __nv_bfloat16 h1 = __float2bfloat16_rn(v.y);
        __nv_bfloat16 h2 = __float2bfloat16_rn(v.z);
        __nv_bfloat16 h3 = __float2bfloat16_rn(v.w);
        __nv_bfloat16 l0 = __float2bfloat16_rn(v.x - __bfloat162float(h0));
        __nv_bfloat16 l1 = __float2bfloat16_rn(v.y - __bfloat162float(h1));
        __nv_bfloat16 l2 = __float2bfloat16_rn(v.z - __bfloat162float(h2));
        __nv_bfloat16 l3 = __float2bfloat16_rn(v.w - __bfloat162float(h3));
        ((__nv_bfloat162*)hi)[2 * i + 0] = __halves2bfloat162(h0, h1);
        ((__nv_bfloat162*)hi)[2 * i + 1] = __halves2bfloat162(h2, h3);
        ((__nv_bfloat162*)lo)[2 * i + 0] = __halves2bfloat162(l0, l1);
        ((__nv_bfloat162*)lo)[2 * i + 1] = __halves2bfloat162(l2, l3);
    }
}

/* ================= GEMM1: xw = x@W^T + bW  (bf16x3 HMMA) =================
   EXACT R10 pipeline (561us): loads for it+1 issued before waiting on it. */
#define GSK 72
#define GT_B (128 * GSK * 2)            /* 18432 B per tile array */
#define GBUF_B (4 * GT_B)               /* Ahi,Alo,Bhi,Blo = 73728 B */
#define GEMM_SMEM (2 * GBUF_B)          /* 147456 B */

__device__ __forceinline__ void g1_load_chunk(
    uint32_t sbuf, int tid, int m0, int n0, int it)
{
    const __nv_bfloat16* srcs[4] = {
        g_xhi + (size_t)m0 * Idim, g_xlo + (size_t)m0 * Idim,
        g_whi + (size_t)n0 * Idim, g_wlo + (size_t)n0 * Idim };
#pragma unroll
    for (int arr = 0; arr < 4; ++arr) {
        const __nv_bfloat16* s = srcs[arr] + it * 64;
#pragma unroll
        for (int u = 0; u < 4; ++u) {
            const int i = tid + u * 256;       /* 0..1023 */
            const int r = i >> 3, kq = i & 7;
            CP_ASYNC16(sbuf + arr * GT_B + (r * GSK + kq * 8) * 2,
                       (const char*)(s + (size_t)r * Idim + kq * 8));
        }
    }
}

__global__ __launch_bounds__(256, 1) void gemm_xw_hmma(const float* __restrict__ bW)
{
    extern __shared__ __align__(16) char gsm[];
    const uint32_t sb = smem_u32(gsm);
    const int tid = threadIdx.x;
    const int l = tid & 31, wid = tid >> 5;
    const int wm = wid >> 2, wn = wid & 3;
    const int n0 = blockIdx.x * 128;
    const int m0 = blockIdx.y * 128;

    const int ra = wm * 64 + (l % 16);
    const int ca = (l >> 4) * 8;
    const int rb = wn * 32 + (l & 7);
    const int cb = ((l % 16) >> 3) * 8;

    float C[4][4][4];
#pragma unroll
    for (int a = 0; a < 4; ++a)
#pragma unroll
        for (int b = 0; b < 4; ++b)
#pragma unroll
            for (int c = 0; c < 4; ++c) C[a][b][c] = 0.f;

    g1_load_chunk(sb, tid, m0, n0, 0);
    CP_COMMIT();

    for (int it = 0; it < 16; ++it) {
        if (it < 15) {
            g1_load_chunk(sb + ((it + 1) & 1) * GBUF_B, tid, m0, n0, it + 1);
            CP_COMMIT();
            CP_WAIT(1);
        } else {
            CP_WAIT(0);
        }
        __syncthreads();

        const uint32_t buf = sb + (it & 1) * GBUF_B;
        const uint32_t aBaseHi = buf + (ra * GSK + ca) * 2;
        const uint32_t aBaseLo = aBaseHi + GT_B;
        const uint32_t bBaseHi = buf + 2 * GT_B + (rb * GSK + cb) * 2;
        const uint32_t bBaseLo = bBaseHi + GT_B;

#pragma unroll
        for (int s = 0; s < 4; ++s) {
            uint32_t ah[4][4], al[4][4], bh[4][2], bl[4][2];
#pragma unroll
            for (int mi = 0; mi < 4; ++mi) {
                LDSM_X4(ah[mi], aBaseHi + (mi * 16 * GSK + s * 16) * 2);
                LDSM_X4(al[mi], aBaseLo + (mi * 16 * GSK + s * 16) * 2);
            }
#pragma unroll
            for (int nj = 0; nj < 4; ++nj) {
                LDSM_X2(bh[nj], bBaseHi + (nj * 8 * GSK + s * 16) * 2);
                LDSM_X2(bl[nj], bBaseLo + (nj * 8 * GSK + s * 16) * 2);
            }
#pragma unroll
            for (int mi = 0; mi < 4; ++mi)
#pragma unroll
                for (int nj = 0; nj < 4; ++nj) {
                    mma16816(C[mi][nj], ah[mi], bh[nj]);
                    mma16816(C[mi][nj], ah[mi], bl[nj]);
                    mma16816(C[mi][nj], al[mi], bh[nj]);
                }
        }
        __syncthreads();
    }

    const int g = l >> 2, tig = l & 3;
#pragma unroll
    for (int mi = 0; mi < 4; ++mi)
#pragma unroll
        for (int nj = 0; nj < 4; ++nj) {
            const int row = m0 + wm * 64 + mi * 16 + g;
            const int col = n0 + wn * 32 + nj * 8 + 2 * tig;
            const float2 bw = *(const float2*)&bW[col];
            float2 v0, v1;
            v0.x = C[mi][nj][0] + bw.x; v0.y = C[mi][nj][1] + bw.y;
            v1.x = C[mi][nj][2] + bw.x; v1.y = C[mi][nj][3] + bw.y;
            *(float2*)&g_xw[(size_t)row * Hdim + col] = v0;
            *(float2*)&g_xw[(size_t)(row + 8) * Hdim + col] = v1;
        }
}

/* ================= Persistent recurrence (bf16x3 HMMA) =================
   Grid (32 col-groups, 4 batch-groups) = 128 CTAs, 512 thr (16 warps).
   Warp w consumes h cols [64w,64w+64) = slices of producer CTAs 2w,2w+1 only:
   each warp polls just its TWO producer flags -> pipelined cross-CTA dataflow.
   WAR on ping-pong is safe: the pre-reduce __syncthreads implies all 16 warps
   passed their polls => all 32 flags >= t => nobody still reads h(t-2). */
#define RB 16
#define RC 32
#define GRP 32
#define RTHREADS 512
#define SK 1032                          /* smem k-stride in bf16 (2064B == 16 mod 128) */
#define UHI_OFF 0
#define ULO_OFF (RC * SK * 2)            /* 66048 */
#define HHI_OFF (2 * RC * SK * 2)        /* 132096 */
#define HLO_OFF (HHI_OFF + RB * SK * 2)  /* 165120 */
#define BU_OFF  (HLO_OFF + RB * SK * 2)  /* 198144 */
#define RNN_SMEM (BU_OFF + 256)
#define RST 34                           /* reduce row stride, floats */
#define RWB (16 * RST)                   /* per-warp reduce block = 544 floats */

__global__ __launch_bounds__(RTHREADS, 1) void rnn_steps_hmma(
    const float* __restrict__ bU, float* __restrict__ out)
{
    extern __shared__ __align__(16) char rsm[];
    const uint32_t sb = smem_u32(rsm);
    float* bUs = (float*)(rsm + BU_OFF);
    float* red = (float*)(rsm + HHI_OFF);   /* aliases H region post-MMA */

    const int tid = threadIdx.x;
    const int l = tid & 31, w = tid >> 5;
    const int cx = blockIdx.x;
    const int c0 = cx * RC;
    const int bg = blockIdx.y;
    const int b0 = bg * RB;
    float* out1 = out;
    float* out2 = out + (size_t)M_TOT * Hdim;

    /* one-time: load U hi/lo slice [32 n][1024 k] into padded SMEM */
#pragma unroll
    for (int u = 0; u < 16; ++u) {
        const int i = tid + u * RTHREADS;      /* 0..8191 */
        const int arr = i >> 12, rem = i & 4095;
        const int r = rem >> 7, kq = rem & 127;
        const __nv_bfloat16* s = (arr ? g_ulo : g_uhi) + (size_t)(c0 + r) * Hdim + kq * 8;
        uint4 v = *(const uint4*)s;
        *(uint4*)(rsm + (arr ? ULO_OFF : UHI_OFF) + (r * SK + kq * 8) * 2) = v;
    }
    if (tid < RC) bUs[tid] = bU[c0 + tid];

    /* monotonic base: own flag only (self-written) -> uniform across group */
    const unsigned base = g_flag[bg][cx];
    __syncthreads();

    const int ob = tid >> 5;      /* output batch 0..15 */
    const int oc = tid & 31;      /* output col   0..31 */
    const int g = l >> 2, tig = l & 3;

    /* per-lane fragment address bases */
    const uint32_t aHiB = sb + HHI_OFF + ((l % 16) * SK + (l >> 4) * 8 + w * 64) * 2;
    const uint32_t aLoB = aHiB + (HLO_OFF - HHI_OFF);
    const uint32_t bHiB = sb + UHI_OFF + ((l & 7) * SK + ((l % 16) >> 3) * 8 + w * 64) * 2;
    const uint32_t bLoB = bHiB + ULO_OFF;

    /* producer flags for this warp's k-slice */
    const unsigned* myflag = (const unsigned*)&g_flag[bg][2 * w + (l & 1)];

    /* ---- t = 0 : h = tanh(xw) ---- */
    {
        const size_t idx = ((size_t)(b0 + ob) * Tdim + 0) * Hdim + (c0 + oc);
        const float h = tanhf(g_xw[idx]);
        const __nv_bfloat16 hi = __float2bfloat16_rn(h);
        const __nv_bfloat16 lo = __float2bfloat16_rn(h - __bfloat162float(hi));
        g_hhi[0][(b0 + ob) * Hdim + c0 + oc] = hi;
        g_hlo[0][(b0 + ob) * Hdim + c0 + oc] = lo;
        __syncthreads();
        if (tid == 0) { __threadfence(); g_flag[bg][cx] = base + 1; }
        out1[idx] = h;
    }

    for (int t = 1; t < Tdim; ++t) {
        /* xw prefetch: independent of flags */
        const size_t oidx = ((size_t)(b0 + ob) * Tdim + t) * Hdim + (c0 + oc);
        const float xwv = __ldg(&g_xw[oidx]);

        /* wait for THIS warp's two producers only */
        if (l < 2) {
            const unsigned target = base + (unsigned)t;
            unsigned v;
            do {
                asm volatile("ld.global.acquire.gpu.u32 %0, [%1];" : "=r"(v) : "l"(myflag) : "memory");
            } while ((int)(v - target) < 0);
        }
        __syncwarp();

        /* per-warp staging of OWN k-slice [16 b][64 k] hi+lo */
        const int pp = (t - 1) & 1;
        const int kb = w * 64;
#pragma unroll
        for (int u = 0; u < 8; ++u) {
            const int idx = u * 32 + l;            /* 0..255 */
            const int arr = idx >> 7, rem = idx & 127;
            const int r = rem >> 3, kq = rem & 7;
            const __nv_bfloat16* s = (arr ? g_hlo[pp] : g_hhi[pp])
                                     + (size_t)(b0 + r) * Hdim + kb + kq * 8;
            uint4 v = *(const uint4*)s;
            *(uint4*)(rsm + (arr ? HLO_OFF : HHI_OFF) + (r * SK + kb + kq * 8) * 2) = v;
        }
        __syncwarp();

        /* HMMA: warp w covers its k-slice, 4 n-tiles of 8 */
        float C[4][4];
#pragma unroll
        for (int a = 0; a < 4; ++a)
#pragma unroll
            for (int c = 0; c < 4; ++c) C[a][c] = 0.f;
#pragma unroll
        for (int s = 0; s < 4; ++s) {
            uint32_t ah[4], al[4];
            LDSM_X4(ah, aHiB + s * 32);
            LDSM_X4(al, aLoB + s * 32);
#pragma unroll
            for (int nj = 0; nj < 4; ++nj) {
                uint32_t bh[2], bl[2];
                LDSM_X2(bh, bHiB + nj * (8 * SK * 2) + s * 32);
                LDSM_X2(bl, bLoB + nj * (8 * SK * 2) + s * 32);
                mma16816(C[nj], ah, bh);
                mma16816(C[nj], ah, bl);
                mma16816(C[nj], al, bh);
            }
        }
        /* all warps done reading H smem (and hence all flags >= t) */
        __syncthreads();

        /* write C frags to reduce buffer */
#pragma unroll
        for (int nj = 0; nj < 4; ++nj) {
            float2 v0, v1;
            v0.x = C[nj][0]; v0.y = C[nj][1];
            v1.x = C[nj][2]; v1.y = C[nj][3];
            *(float2*)&red[w * RWB + g * RST + nj * 8 + 2 * tig] = v0;
            *(float2*)&red[w * RWB + (g + 8) * RST + nj * 8 + 2 * tig] = v1;
        }
        __syncthreads();

        /* reduce 16 k-splits + epilogue */
        float sum = 0.f;
#pragma unroll
        for (int r = 0; r < 16; ++r) sum += red[r * RWB + ob * RST + oc];
        sum += bUs[oc];
        const float h = tanhf(xwv + sum);
        const __nv_bfloat16 hi = __float2bfloat16_rn(h);
        const __nv_bfloat16 lo = __float2bfloat16_rn(h - __bfloat162float(hi));
        g_hhi[t & 1][(b0 + ob) * Hdim + c0 + oc] = hi;
        g_hlo[t & 1][(b0 + ob) * Hdim + c0 + oc] = lo;

        if (t < Tdim - 1) {
            __syncthreads();
            if (tid == 0) { __threadfence(); g_flag[bg][cx] = base + (unsigned)(t + 1); }
        }
        /* output stores AFTER publish: off the inter-CTA critical path */
        out1[oidx] = h;
        if (t == Tdim - 1) out2[(size_t)(b0 + ob) * Hdim + (c0 + oc)] = h;
    }
}

/* ================= launch ================= */
extern "C" void kernel_launch(void* const* d_in, const int* in_sizes, int n_in,
                              void* d_out, int out_size)
{
    const float* x  = (const float*)d_in[0];
    const float* W  = (const float*)d_in[1];
    const float* bW = (const float*)d_in[2];
    const float* U  = (const float*)d_in[3];
    const float* bU = (const float*)d_in[4];
    float* out = (float*)d_out;

    cvt_split_kernel<<<8192, 256>>>(x, 0, (int)((size_t)M_TOT * Idim / 4));
    cvt_split_kernel<<<1024, 256>>>(W, 1, (int)((size_t)Hdim * Idim / 4));
    cvt_split_kernel<<<1024, 256>>>(U, 2, (int)((size_t)Hdim * Hdim / 4));

    cudaFuncSetAttribute(gemm_xw_hmma,
                         cudaFuncAttributeMaxDynamicSharedMemorySize, GEMM_SMEM);
    gemm_xw_hmma<<<dim3(Hdim / 128, M_TOT / 128), 256, GEMM_SMEM>>>(bW);

    cudaFuncSetAttribute(rnn_steps_hmma,
                         cudaFuncAttributeMaxDynamicSharedMemorySize, RNN_SMEM);
    rnn_steps_hmma<<<dim3(32, 4), RTHREADS, RNN_SMEM>>>(bU, out);
}

// round 15
// speedup vs baseline: 1.4776x; 1.4776x over previous
#include <cuda_runtime.h>
#include <cuda_bf16.h>
#include <math.h>
#include <stdint.h>

#define Bdim 64
#define Tdim 512
#define Idim 1024
#define Hdim 1024
#define M_TOT (Bdim*Tdim)   /* 32768 */

typedef unsigned long long u64;

/* ================= PTX helpers (all base-sm_103-safe: sm_80 era) ================= */
__device__ __forceinline__ uint32_t smem_u32(const void* p) {
    uint32_t a;
    asm("{ .reg .u64 t; cvta.to.shared.u64 t, %1; cvt.u32.u64 %0, t; }" : "=r"(a) : "l"(p));
    return a;
}
#define LDSM_X4(r, addr) \
    asm volatile("ldmatrix.sync.aligned.m8n8.x4.shared.b16 {%0,%1,%2,%3}, [%4];" \
        : "=r"((r)[0]), "=r"((r)[1]), "=r"((r)[2]), "=r"((r)[3]) : "r"(addr))
#define LDSM_X2(r, addr) \
    asm volatile("ldmatrix.sync.aligned.m8n8.x2.shared.b16 {%0,%1}, [%2];" \
        : "=r"((r)[0]), "=r"((r)[1]) : "r"(addr))
__device__ __forceinline__ void mma16816(float* c, const uint32_t* a, const uint32_t* b) {
    asm volatile(
        "mma.sync.aligned.m16n8k16.row.col.f32.bf16.bf16.f32 "
        "{%0,%1,%2,%3}, {%4,%5,%6,%7}, {%8,%9}, {%0,%1,%2,%3};"
        : "+f"(c[0]), "+f"(c[1]), "+f"(c[2]), "+f"(c[3])
        : "r"(a[0]), "r"(a[1]), "r"(a[2]), "r"(a[3]), "r"(b[0]), "r"(b[1]));
}
#define CP_ASYNC16(dst, src) \
    asm volatile("cp.async.cg.shared.global [%0], [%1], 16;" :: "r"(dst), "l"(src))
#define CP_COMMIT() asm volatile("cp.async.commit_group;" ::: "memory")
#define CP_WAIT(N)  asm volatile("cp.async.wait_group %0;" :: "n"(N) : "memory")

/* ---- scratch (device globals: no allocation allowed) ---- */
__device__ float g_xw[(size_t)M_TOT * Hdim];              /* 128 MB */
__device__ __nv_bfloat16 g_xhi[(size_t)M_TOT * Idim];     /* 64 MB */
__device__ __nv_bfloat16 g_xlo[(size_t)M_TOT * Idim];     /* 64 MB */
__device__ __nv_bfloat16 g_whi[(size_t)Hdim * Idim];
__device__ __nv_bfloat16 g_wlo[(size_t)Hdim * Idim];
__device__ __nv_bfloat16 g_uhi[(size_t)Hdim * Hdim];
__device__ __nv_bfloat16 g_ulo[(size_t)Hdim * Hdim];
__device__ __nv_bfloat16 g_hhi[2][Bdim * Hdim];           /* h3 state hi, ping-pong */
__device__ __nv_bfloat16 g_hlo[2][Bdim * Hdim];           /* h3 state lo */
__device__ unsigned g_cnt4[4][32];                        /* per-batch-group barrier counter */
__device__ volatile unsigned g_gen4[4][32];               /* per-batch-group generation */

/* ================= fp32 -> bf16 hi/lo split ================= */
__global__ __launch_bounds__(256) void cvt_split_kernel(
    const float* __restrict__ src, int which, int n4)
{
    __nv_bfloat16 *hi, *lo;
    if (which == 0)      { hi = g_xhi; lo = g_xlo; }
    else if (which == 1) { hi = g_whi; lo = g_wlo; }
    else                 { hi = g_uhi; lo = g_ulo; }
    for (int i = blockIdx.x * 256 + threadIdx.x; i < n4; i += gridDim.x * 256) {
        float4 v = ((const float4*)src)[i];
        __nv_bfloat16 h0 = __float2bfloat16_rn(v.x);
        __nv_bfloat16 h1 = __float2bfloat16_rn(v.y);
        __nv_bfloat16 h2 = __float2bfloat16_rn(v.z);
        __nv_bfloat16 h3 = __float2bfloat16_rn(v.w);
        __nv_bfloat16 l0 = __float2bfloat16_rn(v.x - __bfloat162float(h0));
        __nv_bfloat16 l1 = __float2bfloat16_rn(v.y - __bfloat162float(h1));
        __nv_bfloat16 l2 = __float2bfloat16_rn(v.z - __bfloat162float(h2));
        __nv_bfloat16 l3 = __float2bfloat16_rn(v.w - __bfloat162float(h3));
        ((__nv_bfloat162*)hi)[2 * i + 0] = __halves2bfloat162(h0, h1);
        ((__nv_bfloat162*)hi)[2 * i + 1] = __halves2bfloat162(h2, h3);
        ((__nv_bfloat162*)lo)[2 * i + 0] = __halves2bfloat162(l0, l1);
        ((__nv_bfloat162*)lo)[2 * i + 1] = __halves2bfloat162(l2, l3);
    }
}

/* ================= GEMM1: xw = x@W^T + bW  (bf16x3 HMMA) =================
   3-buffer cp.async pipeline, ONE syncthreads per K-chunk:
   per iter j: wait(j landed) -> syncthreads -> issue j+2 -> compute j. */
#define GSK 72
#define GT_B (128 * GSK * 2)            /* 18432 B per tile array */
#define GBUF_B (4 * GT_B)               /* Ahi,Alo,Bhi,Blo = 73728 B */
#define GEMM_SMEM (3 * GBUF_B)          /* 221184 B */

__device__ __forceinline__ void g1_load_chunk(
    uint32_t sbuf, int tid, int m0, int n0, int it)
{
    const __nv_bfloat16* srcs[4] = {
        g_xhi + (size_t)m0 * Idim, g_xlo + (size_t)m0 * Idim,
        g_whi + (size_t)n0 * Idim, g_wlo + (size_t)n0 * Idim };
#pragma unroll
    for (int arr = 0; arr < 4; ++arr) {
        const __nv_bfloat16* s = srcs[arr] + it * 64;
#pragma unroll
        for (int u = 0; u < 4; ++u) {
            const int i = tid + u * 256;       /* 0..1023 */
            const int r = i >> 3, kq = i & 7;
            CP_ASYNC16(sbuf + arr * GT_B + (r * GSK + kq * 8) * 2,
                       (const char*)(s + (size_t)r * Idim + kq * 8));
        }
    }
}

__global__ __launch_bounds__(256, 1) void gemm_xw_hmma(const float* __restrict__ bW)
{
    extern __shared__ __align__(16) char gsm[];
    const uint32_t sb = smem_u32(gsm);
    const int tid = threadIdx.x;
    const int l = tid & 31, wid = tid >> 5;
    const int wm = wid >> 2, wn = wid & 3;
    const int n0 = blockIdx.x * 128;
    const int m0 = blockIdx.y * 128;

    const int ra = wm * 64 + (l % 16);
    const int ca = (l >> 4) * 8;
    const int rb = wn * 32 + (l & 7);
    const int cb = ((l % 16) >> 3) * 8;

    float C[4][4][4];
#pragma unroll
    for (int a = 0; a < 4; ++a)
#pragma unroll
        for (int b = 0; b < 4; ++b)
#pragma unroll
            for (int c = 0; c < 4; ++c) C[a][b][c] = 0.f;

    g1_load_chunk(sb, tid, m0, n0, 0);
    CP_COMMIT();
    g1_load_chunk(sb + GBUF_B, tid, m0, n0, 1);
    CP_COMMIT();

    for (int it = 0; it < 16; ++it) {
        if (it < 15) { CP_WAIT(1); } else { CP_WAIT(0); }
        __syncthreads();   /* chunk it visible to all; compute it-1 done -> buffer free */
        if (it < 14) {
            g1_load_chunk(sb + ((it + 2) % 3) * GBUF_B, tid, m0, n0, it + 2);
            CP_COMMIT();
        }

        const uint32_t buf = sb + (it % 3) * GBUF_B;
        const uint32_t aBaseHi = buf + (ra * GSK + ca) * 2;
        const uint32_t aBaseLo = aBaseHi + GT_B;
        const uint32_t bBaseHi = buf + 2 * GT_B + (rb * GSK + cb) * 2;
        const uint32_t bBaseLo = bBaseHi + GT_B;

#pragma unroll
        for (int s = 0; s < 4; ++s) {
            uint32_t ah[4][4], al[4][4], bh[4][2], bl[4][2];
#pragma unroll
            for (int mi = 0; mi < 4; ++mi) {
                LDSM_X4(ah[mi], aBaseHi + (mi * 16 * GSK + s * 16) * 2);
                LDSM_X4(al[mi], aBaseLo + (mi * 16 * GSK + s * 16) * 2);
            }
#pragma unroll
            for (int nj = 0; nj < 4; ++nj) {
                LDSM_X2(bh[nj], bBaseHi + (nj * 8 * GSK + s * 16) * 2);
                LDSM_X2(bl[nj], bBaseLo + (nj * 8 * GSK + s * 16) * 2);
            }
#pragma unroll
            for (int mi = 0; mi < 4; ++mi)
#pragma unroll
                for (int nj = 0; nj < 4; ++nj) {
                    mma16816(C[mi][nj], ah[mi], bh[nj]);
                    mma16816(C[mi][nj], ah[mi], bl[nj]);
                    mma16816(C[mi][nj], al[mi], bh[nj]);
                }
        }
    }

    const int g = l >> 2, tig = l & 3;
#pragma unroll
    for (int mi = 0; mi < 4; ++mi)
#pragma unroll
        for (int nj = 0; nj < 4; ++nj) {
            const int row = m0 + wm * 64 + mi * 16 + g;
            const int col = n0 + wn * 32 + nj * 8 + 2 * tig;
            const float2 bw = *(const float2*)&bW[col];
            float2 v0, v1;
            v0.x = C[mi][nj][0] + bw.x; v0.y = C[mi][nj][1] + bw.y;
            v1.x = C[mi][nj][2] + bw.x; v1.y = C[mi][nj][3] + bw.y;
            *(float2*)&g_xw[(size_t)row * Hdim + col] = v0;
            *(float2*)&g_xw[(size_t)(row + 8) * Hdim + col] = v1;
        }
}

/* ================= Persistent recurrence (bf16x3 HMMA) =================
   R10 skeleton (PROVEN): grid (32,4), 512 thr, counter barrier, CTA-wide staging.
   New: dedicated (non-aliased) reduce buffer -> one less syncthreads per step,
   MMA/STS overlap across warps; barrier arrival before out1/out2 stores. */
#define RB 16
#define RC 32
#define GRP 32
#define RTHREADS 512
#define SK 1032                          /* smem k-stride in bf16 (2064B == 16 mod 128) */
#define UHI_OFF 0
#define ULO_OFF (RC * SK * 2)            /* 66048 */
#define HHI_OFF (2 * RC * SK * 2)        /* 132096 */
#define HLO_OFF (HHI_OFF + RB * SK * 2)  /* 165120 */
#define BU_OFF  (HLO_OFF + RB * SK * 2)  /* 198144 */
#define RED_OFF (BU_OFF + 256)           /* 198400 */
#define RST 33                           /* reduce row stride, floats (odd: scalar STS) */
#define RWB (16 * RST)                   /* per-warp reduce block = 528 floats */
#define RNN_SMEM (RED_OFF + 16 * RWB * 4)   /* 232192 */

__device__ __forceinline__ void group_barrier(int bg, unsigned target)
{
    __syncthreads();
    if (threadIdx.x == 0) {
        __threadfence();
        unsigned prev = atomicAdd(&g_cnt4[bg][0], 1u);
        if (prev == GRP - 1) {
            g_cnt4[bg][0] = 0;
            __threadfence();
            g_gen4[bg][0] = target;            /* release */
        } else {
            while ((int)(g_gen4[bg][0] - target) < 0) {}
            __threadfence();                   /* acquire */
        }
    }
    __syncthreads();
}

__global__ __launch_bounds__(RTHREADS, 1) void rnn_steps_hmma(
    const float* __restrict__ bU, float* __restrict__ out)
{
    extern __shared__ __align__(16) char rsm[];
    const uint32_t sb = smem_u32(rsm);
    float* bUs = (float*)(rsm + BU_OFF);
    float* red = (float*)(rsm + RED_OFF);

    const int tid = threadIdx.x;
    const int l = tid & 31, w = tid >> 5;
    const int cx = blockIdx.x;
    const int c0 = cx * RC;
    const int bg = blockIdx.y;
    const int b0 = bg * RB;
    float* out1 = out;
    float* out2 = out + (size_t)M_TOT * Hdim;

    /* one-time: load U hi/lo slice [32 n][1024 k] into padded SMEM */
#pragma unroll
    for (int u = 0; u < 16; ++u) {
        const int i = tid + u * RTHREADS;      /* 0..8191 */
        const int arr = i >> 12, rem = i & 4095;
        const int r = rem >> 7, kq = rem & 127;
        const __nv_bfloat16* s = (arr ? g_ulo : g_uhi) + (size_t)(c0 + r) * Hdim + kq * 8;
        uint4 v = *(const uint4*)s;
        *(uint4*)(rsm + (arr ? ULO_OFF : UHI_OFF) + (r * SK + kq * 8) * 2) = v;
    }
    if (tid < RC) bUs[tid] = bU[c0 + tid];

    /* barrier base generation (persists across graph replays) */
    const unsigned base = g_gen4[bg][0];
    __syncthreads();

    const int ob = tid >> 5;      /* output batch 0..15 */
    const int oc = tid & 31;      /* output col   0..31 */
    const int g = l >> 2, tig = l & 3;

    /* per-lane fragment address bases */
    const uint32_t aHiB = sb + HHI_OFF + ((l % 16) * SK + (l >> 4) * 8 + w * 64) * 2;
    const uint32_t aLoB = aHiB + (HLO_OFF - HHI_OFF);
    const uint32_t bHiB = sb + UHI_OFF + ((l & 7) * SK + ((l % 16) >> 3) * 8 + w * 64) * 2;
    const uint32_t bLoB = bHiB + ULO_OFF;

    /* ---- t = 0 : h = tanh(xw) ---- */
    unsigned nbar = 0;
    {
        const size_t idx = ((size_t)(b0 + ob) * Tdim + 0) * Hdim + (c0 + oc);
        const float h = tanhf(g_xw[idx]);
        const __nv_bfloat16 hi = __float2bfloat16_rn(h);
        const __nv_bfloat16 lo = __float2bfloat16_rn(h - __bfloat162float(hi));
        g_hhi[0][(b0 + ob) * Hdim + c0 + oc] = hi;
        g_hlo[0][(b0 + ob) * Hdim + c0 + oc] = lo;
        group_barrier(bg, base + (++nbar));
        out1[idx] = h;
    }

    for (int t = 1; t < Tdim; ++t) {
        /* xw prefetch (hides DRAM latency under staging + MMA) */
        const size_t oidx = ((size_t)(b0 + ob) * Tdim + t) * Hdim + (c0 + oc);
        const float xwv = __ldg(&g_xw[oidx]);

        /* stage h3(t-1) hi/lo: [16 b][1024 k] -> padded SMEM (CTA-wide) */
        const int pp = (t - 1) & 1;
#pragma unroll
        for (int u = 0; u < 8; ++u) {
            const int i = tid + u * RTHREADS;   /* 0..4095 */
            const int arr = i >> 11, rem = i & 2047;
            const int r = rem >> 7, kq = rem & 127;
            const __nv_bfloat16* s = (arr ? g_hlo[pp] : g_hhi[pp]) + (size_t)(b0 + r) * Hdim + kq * 8;
            uint4 v = *(const uint4*)s;
            *(uint4*)(rsm + (arr ? HLO_OFF : HHI_OFF) + (r * SK + kq * 8) * 2) = v;
        }
        __syncthreads();

        /* HMMA: warp w covers k in [64w, 64w+64), 4 n-tiles of 8 */
        float C[4][4];
#pragma unroll
        for (int a = 0; a < 4; ++a)
#pragma unroll
            for (int c = 0; c < 4; ++c) C[a][c] = 0.f;
#pragma unroll
        for (int s = 0; s < 4; ++s) {
            uint32_t ah[4], al[4];
            LDSM_X4(ah, aHiB + s * 32);
            LDSM_X4(al, aLoB + s * 32);
#pragma unroll
            for (int nj = 0; nj < 4; ++nj) {
                uint32_t bh[2], bl[2];
                LDSM_X2(bh, bHiB + nj * (8 * SK * 2) + s * 32);
                LDSM_X2(bl, bLoB + nj * (8 * SK * 2) + s * 32);
                mma16816(C[nj], ah, bh);
                mma16816(C[nj], ah, bl);
                mma16816(C[nj], al, bh);
            }
        }

        /* write C frags to dedicated reduce buffer (no pre-sync needed) */
#pragma unroll
        for (int nj = 0; nj < 4; ++nj) {
            red[w * RWB + g * RST + nj * 8 + 2 * tig]           = C[nj][0];
            red[w * RWB + g * RST + nj * 8 + 2 * tig + 1]       = C[nj][1];
            red[w * RWB + (g + 8) * RST + nj * 8 + 2 * tig]     = C[nj][2];
            red[w * RWB + (g + 8) * RST + nj * 8 + 2 * tig + 1] = C[nj][3];
        }
        __syncthreads();

        /* reduce 16 k-splits + epilogue */
        float sum = 0.f;
#pragma unroll
        for (int r = 0; r < 16; ++r) sum += red[r * RWB + ob * RST + oc];
        sum += bUs[oc];
        const float h = tanhf(xwv + sum);
        const __nv_bfloat16 hi = __float2bfloat16_rn(h);
        const __nv_bfloat16 lo = __float2bfloat16_rn(h - __bfloat162float(hi));
        g_hhi[t & 1][(b0 + ob) * Hdim + c0 + oc] = hi;
        g_hlo[t & 1][(b0 + ob) * Hdim + c0 + oc] = lo;

        if (t < Tdim - 1) group_barrier(bg, base + (++nbar));

        /* output stores after the arrival: off the inter-CTA critical path */
        out1[oidx] = h;
        if (t == Tdim - 1) out2[(size_t)(b0 + ob) * Hdim + (c0 + oc)] = h;
    }
}

/* ================= launch ================= */
extern "C" void kernel_launch(void* const* d_in, const int* in_sizes, int n_in,
                              void* d_out, int out_size)
{
    const float* x  = (const float*)d_in[0];
    const float* W  = (const float*)d_in[1];
    const float* bW = (const float*)d_in[2];
    const float* U  = (const float*)d_in[3];
    const float* bU = (const float*)d_in[4];
    float* out = (float*)d_out;

    cvt_split_kernel<<<8192, 256>>>(x, 0, (int)((size_t)M_TOT * Idim / 4));
    cvt_split_kernel<<<1024, 256>>>(W, 1, (int)((size_t)Hdim * Idim / 4));
    cvt_split_kernel<<<1024, 256>>>(U, 2, (int)((size_t)Hdim * Hdim / 4));

    cudaFuncSetAttribute(gemm_xw_hmma,
                         cudaFuncAttributeMaxDynamicSharedMemorySize, GEMM_SMEM);
    gemm_xw_hmma<<<dim3(Hdim / 128, M_TOT / 128), 256, GEMM_SMEM>>>(bW);

    cudaFuncSetAttribute(rnn_steps_hmma,
                         cudaFuncAttributeMaxDynamicSharedMemorySize, RNN_SMEM);
    rnn_steps_hmma<<<dim3(32, 4), RTHREADS, RNN_SMEM>>>(bU, out);
}

// round 17
// speedup vs baseline: 1.5613x; 1.0566x over previous
#include <cuda_runtime.h>
#include <cuda_bf16.h>
#include <math.h>
#include <stdint.h>

#define Bdim 64
#define Tdim 512
#define Idim 1024
#define Hdim 1024
#define M_TOT (Bdim*Tdim)   /* 32768 */

typedef unsigned long long u64;

/* ================= PTX helpers (all base-sm_103-safe: sm_80 era) ================= */
__device__ __forceinline__ uint32_t smem_u32(const void* p) {
    uint32_t a;
    asm("{ .reg .u64 t; cvta.to.shared.u64 t, %1; cvt.u32.u64 %0, t; }" : "=r"(a) : "l"(p));
    return a;
}
#define LDSM_X4(r, addr) \
    asm volatile("ldmatrix.sync.aligned.m8n8.x4.shared.b16 {%0,%1,%2,%3}, [%4];" \
        : "=r"((r)[0]), "=r"((r)[1]), "=r"((r)[2]), "=r"((r)[3]) : "r"(addr))
#define LDSM_X2(r, addr) \
    asm volatile("ldmatrix.sync.aligned.m8n8.x2.shared.b16 {%0,%1}, [%2];" \
        : "=r"((r)[0]), "=r"((r)[1]) : "r"(addr))
__device__ __forceinline__ void mma16816(float* c, const uint32_t* a, const uint32_t* b) {
    asm volatile(
        "mma.sync.aligned.m16n8k16.row.col.f32.bf16.bf16.f32 "
        "{%0,%1,%2,%3}, {%4,%5,%6,%7}, {%8,%9}, {%0,%1,%2,%3};"
        : "+f"(c[0]), "+f"(c[1]), "+f"(c[2]), "+f"(c[3])
        : "r"(a[0]), "r"(a[1]), "r"(a[2]), "r"(a[3]), "r"(b[0]), "r"(b[1]));
}
__device__ __forceinline__ void imma16832(int* c, const uint32_t* a, const uint32_t* b) {
    asm volatile(
        "mma.sync.aligned.m16n8k32.row.col.s32.s8.s8.s32 "
        "{%0,%1,%2,%3}, {%4,%5,%6,%7}, {%8,%9}, {%0,%1,%2,%3};"
        : "+r"(c[0]), "+r"(c[1]), "+r"(c[2]), "+r"(c[3])
        : "r"(a[0]), "r"(a[1]), "r"(a[2]), "r"(a[3]), "r"(b[0]), "r"(b[1]));
}
#define CP_ASYNC16(dst, src) \
    asm volatile("cp.async.cg.shared.global [%0], [%1], 16;" :: "r"(dst), "l"(src))
#define CP_COMMIT() asm volatile("cp.async.commit_group;" ::: "memory")
#define CP_WAIT(N)  asm volatile("cp.async.wait_group %0;" :: "n"(N) : "memory")

/* ---- scratch (device globals: no allocation allowed) ---- */
__device__ float g_xw[(size_t)M_TOT * Hdim];              /* 128 MB */
__device__ __nv_bfloat16 g_xhi[(size_t)M_TOT * Idim];     /* 64 MB */
__device__ __nv_bfloat16 g_xlo[(size_t)M_TOT * Idim];     /* 64 MB */
__device__ __nv_bfloat16 g_whi[(size_t)Hdim * Idim];
__device__ __nv_bfloat16 g_wlo[(size_t)Hdim * Idim];
__device__ signed char g_ua[(size_t)Hdim * Hdim];         /* U int8 hi (x256) */
__device__ signed char g_ub[(size_t)Hdim * Hdim];         /* U int8 lo */
__device__ signed char g_ha[2][Bdim * Hdim];              /* h int8 hi, ping-pong */
__device__ signed char g_hb[2][Bdim * Hdim];              /* h int8 lo */
__device__ unsigned g_cnt4[4][32];                        /* per-batch-group barrier counter */
__device__ volatile unsigned g_gen4[4][32];               /* per-batch-group generation */

/* ================= fp32 -> bf16 hi/lo split (x, W) ================= */
__global__ __launch_bounds__(256) void cvt_split_kernel(
    const float* __restrict__ src, int which, int n4)
{
    __nv_bfloat16 *hi, *lo;
    if (which == 0) { hi = g_xhi; lo = g_xlo; }
    else            { hi = g_whi; lo = g_wlo; }
    for (int i = blockIdx.x * 256 + threadIdx.x; i < n4; i += gridDim.x * 256) {
        float4 v = ((const float4*)src)[i];
        __nv_bfloat16 h0 = __float2bfloat16_rn(v.x);
        __nv_bfloat16 h1 = __float2bfloat16_rn(v.y);
        __nv_bfloat16 h2 = __float2bfloat16_rn(v.z);
        __nv_bfloat16 h3 = __float2bfloat16_rn(v.w);
        __nv_bfloat16 l0 = __float2bfloat16_rn(v.x - __bfloat162float(h0));
        __nv_bfloat16 l1 = __float2bfloat16_rn(v.y - __bfloat162float(h1));
        __nv_bfloat16 l2 = __float2bfloat16_rn(v.z - __bfloat162float(h2));
        __nv_bfloat16 l3 = __float2bfloat16_rn(v.w - __bfloat162float(h3));
        ((__nv_bfloat162*)hi)[2 * i + 0] = __halves2bfloat162(h0, h1);
        ((__nv_bfloat162*)hi)[2 * i + 1] = __halves2bfloat162(h2, h3);
        ((__nv_bfloat162*)lo)[2 * i + 0] = __halves2bfloat162(l0, l1);
        ((__nv_bfloat162*)lo)[2 * i + 1] = __halves2bfloat162(l2, l3);
    }
}

/* ================= U -> int8 pair split: U ~= (ua*256+ub) * 2^-19 ================= */
__global__ __launch_bounds__(256) void cvt_u_int8_kernel(const float* __restrict__ U, int n4)
{
    for (int i = blockIdx.x * 256 + threadIdx.x; i < n4; i += gridDim.x * 256) {
        float4 v = ((const float4*)U)[i];
        int q0 = __float2int_rn(v.x * 524288.f);
        int q1 = __float2int_rn(v.y * 524288.f);
        int q2 = __float2int_rn(v.z * 524288.f);
        int q3 = __float2int_rn(v.w * 524288.f);
        int a0 = (q0 + 128) >> 8, a1 = (q1 + 128) >> 8;
        int a2 = (q2 + 128) >> 8, a3 = (q3 + 128) >> 8;
        uchar4 ua, ub;
        ua.x = (unsigned char)(signed char)a0; ua.y = (unsigned char)(signed char)a1;
        ua.z = (unsigned char)(signed char)a2; ua.w = (unsigned char)(signed char)a3;
        ub.x = (unsigned char)(signed char)(q0 - (a0 << 8));
        ub.y = (unsigned char)(signed char)(q1 - (a1 << 8));
        ub.z = (unsigned char)(signed char)(q2 - (a2 << 8));
        ub.w = (unsigned char)(signed char)(q3 - (a3 << 8));
        ((uchar4*)g_ua)[i] = ua;
        ((uchar4*)g_ub)[i] = ub;
    }
}

/* ================= GEMM1: xw = x@W^T + bW  (bf16x3 HMMA) =================
   VERBATIM R10 pipeline (559us): issue loads for it+1 BEFORE waiting on it. */
#define GSK 72
#define GT_B (128 * GSK * 2)            /* 18432 B per tile array */
#define GBUF_B (4 * GT_B)               /* Ahi,Alo,Bhi,Blo = 73728 B */
#define GEMM_SMEM (2 * GBUF_B)          /* 147456 B */

__device__ __forceinline__ void g1_load_chunk(
    uint32_t sbuf, int tid, int m0, int n0, int it)
{
    const __nv_bfloat16* srcs[4] = {
        g_xhi + (size_t)m0 * Idim, g_xlo + (size_t)m0 * Idim,
        g_whi + (size_t)n0 * Idim, g_wlo + (size_t)n0 * Idim };
#pragma unroll
    for (int arr = 0; arr < 4; ++arr) {
        const __nv_bfloat16* s = srcs[arr] + it * 64;
#pragma unroll
        for (int u = 0; u < 4; ++u) {
            const int i = tid + u * 256;       /* 0..1023 */
            const int r = i >> 3, kq = i & 7;
            CP_ASYNC16(sbuf + arr * GT_B + (r * GSK + kq * 8) * 2,
                       (const char*)(s + (size_t)r * Idim + kq * 8));
        }
    }
}

__global__ __launch_bounds__(256, 1) void gemm_xw_hmma(const float* __restrict__ bW)
{
    extern __shared__ __align__(16) char gsm[];
    const uint32_t sb = smem_u32(gsm);
    const int tid = threadIdx.x;
    const int l = tid & 31, wid = tid >> 5;
    const int wm = wid >> 2, wn = wid & 3;
    const int n0 = blockIdx.x * 128;
    const int m0 = blockIdx.y * 128;

    const int ra = wm * 64 + (l % 16);
    const int ca = (l >> 4) * 8;
    const int rb = wn * 32 + (l & 7);
    const int cb = ((l % 16) >> 3) * 8;

    float C[4][4][4];
#pragma unroll
    for (int a = 0; a < 4; ++a)
#pragma unroll
        for (int b = 0; b < 4; ++b)
#pragma unroll
            for (int c = 0; c < 4; ++c) C[a][b][c] = 0.f;

    g1_load_chunk(sb, tid, m0, n0, 0);
    CP_COMMIT();

    for (int it = 0; it < 16; ++it) {
        if (it < 15) {
            g1_load_chunk(sb + ((it + 1) & 1) * GBUF_B, tid, m0, n0, it + 1);
            CP_COMMIT();
            CP_WAIT(1);
        } else {
            CP_WAIT(0);
        }
        __syncthreads();

        const uint32_t buf = sb + (it & 1) * GBUF_B;
        const uint32_t aBaseHi = buf + (ra * GSK + ca) * 2;
        const uint32_t aBaseLo = aBaseHi + GT_B;
        const uint32_t bBaseHi = buf + 2 * GT_B + (rb * GSK + cb) * 2;
        const uint32_t bBaseLo = bBaseHi + GT_B;

#pragma unroll
        for (int s = 0; s < 4; ++s) {
            uint32_t ah[4][4], al[4][4], bh[4][2], bl[4][2];
#pragma unroll
            for (int mi = 0; mi < 4; ++mi) {
                LDSM_X4(ah[mi], aBaseHi + (mi * 16 * GSK + s * 16) * 2);
                LDSM_X4(al[mi], aBaseLo + (mi * 16 * GSK + s * 16) * 2);
            }
#pragma unroll
            for (int nj = 0; nj < 4; ++nj) {
                LDSM_X2(bh[nj], bBaseHi + (nj * 8 * GSK + s * 16) * 2);
                LDSM_X2(bl[nj], bBaseLo + (nj * 8 * GSK + s * 16) * 2);
            }
#pragma unroll
            for (int mi = 0; mi < 4; ++mi)
#pragma unroll
                for (int nj = 0; nj < 4; ++nj) {
                    mma16816(C[mi][nj], ah[mi], bh[nj]);
                    mma16816(C[mi][nj], ah[mi], bl[nj]);
                    mma16816(C[mi][nj], al[mi], bh[nj]);
                }
        }
        __syncthreads();
    }

    const int g = l >> 2, tig = l & 3;
#pragma unroll
    for (int mi = 0; mi < 4; ++mi)
#pragma unroll
        for (int nj = 0; nj < 4; ++nj) {
            const int row = m0 + wm * 64 + mi * 16 + g;
            const int col = n0 + wn * 32 + nj * 8 + 2 * tig;
            const float2 bw = *(const float2*)&bW[col];
            float2 v0, v1;
            v0.x = C[mi][nj][0] + bw.x; v0.y = C[mi][nj][1] + bw.y;
            v1.x = C[mi][nj][2] + bw.x; v1.y = C[mi][nj][3] + bw.y;
            *(float2*)&g_xw[(size_t)row * Hdim + col] = v0;
            *(float2*)&g_xw[(size_t)(row + 8) * Hdim + col] = v1;
        }
}

/* ================= Persistent recurrence (int8 IMMA, exact split) =================
   R10 skeleton verbatim (grid (32,4), 512 thr, counter barrier, CTA staging,
   same sync sequence). Math: s = sum_k h[k]*U[c][k], with
   h ~= (ha*256+hb)*2^-14, U ~= (ua*256+ub)*2^-19 (int8 pairs, exact),
   3 IMMA passes per k32: Cm += ha*ua ; Cc += ha*ub ; Cc += hb*ua.
   s = Cm*2^-17 + Cc*2^-25 (dropped hb*ub ~ 2^-16/term). */
#define RB 16
#define RC 32
#define GRP 32
#define RTHREADS 512
#define SKB 1040                         /* int8 row stride bytes (1040 % 128 == 16) */
#define UA_OFF 0
#define UB_OFF (RC * SKB)                /* 33280 */
#define HA_OFF (2 * RC * SKB)            /* 66560 */
#define HB_OFF (HA_OFF + RB * SKB)       /* 83200 */
#define BU_OFF (HB_OFF + RB * SKB)       /* 99840 */
#define RED_OFF (BU_OFF + 128)           /* 99968 */
#define RST 34                           /* reduce row stride, floats */
#define RWB (16 * RST)                   /* per-warp reduce block = 544 floats */
#define RNN_SMEM (RED_OFF + 16 * RWB * 4)   /* 134784 */

__device__ __forceinline__ void group_barrier(int bg, unsigned target)
{
    __syncthreads();
    if (threadIdx.x == 0) {
        __threadfence();
        unsigned prev = atomicAdd(&g_cnt4[bg][0], 1u);
        if (prev == GRP - 1) {
            g_cnt4[bg][0] = 0;
            __threadfence();
            g_gen4[bg][0] = target;            /* release */
        } else {
            while ((int)(g_gen4[bg][0] - target) < 0) {}
            __threadfence();                   /* acquire */
        }
    }
    __syncthreads();
}

__global__ __launch_bounds__(RTHREADS, 1) void rnn_steps_imma(
    const float* __restrict__ bU, float* __restrict__ out)
{
    extern __shared__ __align__(16) char rsm[];
    const uint32_t sb = smem_u32(rsm);
    float* bUs = (float*)(rsm + BU_OFF);
    float* red = (float*)(rsm + RED_OFF);

    const int tid = threadIdx.x;
    const int l = tid & 31, w = tid >> 5;
    const int cx = blockIdx.x;
    const int c0 = cx * RC;
    const int bg = blockIdx.y;
    const int b0 = bg * RB;
    float* out1 = out;
    float* out2 = out + (size_t)M_TOT * Hdim;

    /* one-time: load U int8 pair slice [32 n][1024 k] into padded SMEM */
#pragma unroll
    for (int u = 0; u < 8; ++u) {
        const int i = tid + u * RTHREADS;      /* 0..4095 */
        const int arr = i >> 11, rem = i & 2047;
        const int r = rem >> 6, q = rem & 63;  /* r: n-row 0..31, q: 16B chunk */
        const signed char* s = (arr ? g_ub : g_ua) + (size_t)(c0 + r) * Hdim + q * 16;
        uint4 v = *(const uint4*)s;
        *(uint4*)(rsm + (arr ? UB_OFF : UA_OFF) + r * SKB + q * 16) = v;
    }
    if (tid < RC) bUs[tid] = bU[c0 + tid];

    /* barrier base generation (persists across graph replays) */
    const unsigned base = g_gen4[bg][0];
    __syncthreads();

    const int ob = tid >> 5;      /* output batch 0..15 */
    const int oc = tid & 31;      /* output col   0..31 */
    const int g = l >> 2, tig = l & 3;

    /* per-lane fragment address bases (warp w: k-slice bytes [64w, 64w+64)) */
    const uint32_t aA = sb + HA_OFF + (l % 16) * SKB + (l >> 4) * 16 + w * 64;
    const uint32_t aB = aA + (HB_OFF - HA_OFF);
    const uint32_t bA = sb + UA_OFF + (l & 7) * SKB + ((l % 16) >> 3) * 16 + w * 64;
    const uint32_t bB = bA + (UB_OFF - UA_OFF);

    /* ---- t = 0 : h = tanh(xw) ---- */
    unsigned nbar = 0;
    {
        const size_t idx = ((size_t)(b0 + ob) * Tdim + 0) * Hdim + (c0 + oc);
        const float h = tanhf(g_xw[idx]);
        out1[idx] = h;
        const int hi16 = __float2int_rn(h * 16384.f);
        const int ha = (hi16 + 128) >> 8;
        g_ha[0][(b0 + ob) * Hdim + c0 + oc] = (signed char)ha;
        g_hb[0][(b0 + ob) * Hdim + c0 + oc] = (signed char)(hi16 - (ha << 8));
        group_barrier(bg, base + (++nbar));
    }

    for (int t = 1; t < Tdim; ++t) {
        /* xw prefetch (hides DRAM latency under staging + MMA) */
        const size_t oidx = ((size_t)(b0 + ob) * Tdim + t) * Hdim + (c0 + oc);
        const float xwv = __ldg(&g_xw[oidx]);

        /* stage h(t-1) int8 pair: [16 b][1024 k] -> padded SMEM (CTA-wide) */
        const int pp = (t - 1) & 1;
#pragma unroll
        for (int u = 0; u < 4; ++u) {
            const int i = tid + u * RTHREADS;   /* 0..2047 */
            const int arr = i >> 10, rem = i & 1023;
            const int r = rem >> 6, q = rem & 63;
            const signed char* s = (arr ? g_hb[pp] : g_ha[pp]) + (size_t)(b0 + r) * Hdim + q * 16;
            uint4 v = *(const uint4*)s;
            *(uint4*)(rsm + (arr ? HB_OFF : HA_OFF) + r * SKB + q * 16) = v;
        }
        __syncthreads();

        /* IMMA: warp w covers k bytes [64w,64w+64) = 2 k32 steps, 4 n-tiles */
        int Cm[4][4], Cc[4][4];
#pragma unroll
        for (int a = 0; a < 4; ++a)
#pragma unroll
            for (int c = 0; c < 4; ++c) { Cm[a][c] = 0; Cc[a][c] = 0; }
#pragma unroll
        for (int s = 0; s < 2; ++s) {
            uint32_t ha[4], hb[4];
            LDSM_X4(ha, aA + s * 32);
            LDSM_X4(hb, aB + s * 32);
#pragma unroll
            for (int nj = 0; nj < 4; ++nj) {
                uint32_t ua[2], ub[2];
                LDSM_X2(ua, bA + nj * (8 * SKB) + s * 32);
                LDSM_X2(ub, bB + nj * (8 * SKB) + s * 32);
                imma16832(Cm[nj], ha, ua);
                imma16832(Cc[nj], ha, ub);
                imma16832(Cc[nj], hb, ua);
            }
        }
        __syncthreads();

        /* write scaled partials to reduce buffer */
#pragma unroll
        for (int nj = 0; nj < 4; ++nj) {
            float2 v0, v1;
            v0.x = (float)Cm[nj][0] * 7.62939453125e-06f + (float)Cc[nj][0] * 2.9802322387695312e-08f;
            v0.y = (float)Cm[nj][1] * 7.62939453125e-06f + (float)Cc[nj][1] * 2.9802322387695312e-08f;
            v1.x = (float)Cm[nj][2] * 7.62939453125e-06f + (float)Cc[nj][2] * 2.9802322387695312e-08f;
            v1.y = (float)Cm[nj][3] * 7.62939453125e-06f + (float)Cc[nj][3] * 2.9802322387695312e-08f;
            *(float2*)&red[w * RWB + g * RST + nj * 8 + 2 * tig] = v0;
            *(float2*)&red[w * RWB + (g + 8) * RST + nj * 8 + 2 * tig] = v1;
        }
        __syncthreads();

        /* reduce 16 k-splits + epilogue */
        float sum = 0.f;
#pragma unroll
        for (int r = 0; r < 16; ++r) sum += red[r * RWB + ob * RST + oc];
        sum += bUs[oc];
        const float h = tanhf(xwv + sum);
        out1[oidx] = h;
        const int hi16 = __float2int_rn(h * 16384.f);
        const int ha = (hi16 + 128) >> 8;
        g_ha[t & 1][(b0 + ob) * Hdim + c0 + oc] = (signed char)ha;
        g_hb[t & 1][(b0 + ob) * Hdim + c0 + oc] = (signed char)(hi16 - (ha << 8));
        if (t == Tdim - 1) out2[(size_t)(b0 + ob) * Hdim + (c0 + oc)] = h;

        if (t < Tdim - 1) group_barrier(bg, base + (++nbar));
    }
}

/* ================= launch ================= */
extern "C" void kernel_launch(void* const* d_in, const int* in_sizes, int n_in,
                              void* d_out, int out_size)
{
    const float* x  = (const float*)d_in[0];
    const float* W  = (const float*)d_in[1];
    const float* bW = (const float*)d_in[2];
    const float* U  = (const float*)d_in[3];
    const float* bU = (const float*)d_in[4];
    float* out = (float*)d_out;

    cvt_split_kernel<<<8192, 256>>>(x, 0, (int)((size_t)M_TOT * Idim / 4));
    cvt_split_kernel<<<1024, 256>>>(W, 1, (int)((size_t)Hdim * Idim / 4));
    cvt_u_int8_kernel<<<1024, 256>>>(U, (int)((size_t)Hdim * Hdim / 4));

    cudaFuncSetAttribute(gemm_xw_hmma,
                         cudaFuncAttributeMaxDynamicSharedMemorySize, GEMM_SMEM);
    gemm_xw_hmma<<<dim3(Hdim / 128, M_TOT / 128), 256, GEMM_SMEM>>>(bW);

    cudaFuncSetAttribute(rnn_steps_imma,
                         cudaFuncAttributeMaxDynamicSharedMemorySize, RNN_SMEM);
    rnn_steps_imma<<<dim3(32, 4), RTHREADS, RNN_SMEM>>>(bU, out);
}